// round 3
// baseline (speedup 1.0000x reference)
#include <cuda_runtime.h>

#define DIM 512
#define TIME_DIM 2
#define NB 512
#define NK 128
#define EPSF 1e-6f
#define MARGINF 2.0f

__device__ __forceinline__ float dot4(float4 a, float4 b) {
    return a.x*b.x + a.y*b.y + a.z*b.z + a.w*b.w;
}
__device__ __forceinline__ float sq4(float4 a) {
    return a.x*a.x + a.y*a.y + a.z*a.z + a.w*a.w;
}

// per-tail scalar epilogue: mirrors reference manhattan_sqdist on both orders
__device__ __forceinline__ float tail_dist(float sq, float dp, float t1,
                                           float X0, float X1, float NX) {
    // a = -t1^2 + sum_{i>=2} t_i^2
    float a = sq - t1*t1;
    float ct, st;
    if (a > 0.f) {
        float sp = sqrtf(fmaxf(a, EPSF));
        ct = coshf(sp);
        st = sinhf(sp) / sp;
    } else {
        float q = sqrtf(fmaxf(-a, EPSF));
        ct = cosf(q);
        st = sinf(q) / q;
    }
    float y0 = ct;
    float y1 = st * t1;
    float ny = sqrtf(y0*y0 + y1*y1);
    float dt = X0*y0 + X1*y1;
    float ca = fminf(fmaxf(dt / (NX * ny), -1.f + EPSF), 1.f - EPSF);
    float ang = acosf(ca);
    float inner = NX * ny - st * dp;          // xs . ys = st * (x_s . t_raw_s)
    float dh = acoshf(fmaxf(inner, 1.f + EPSF));
    float d1 = NX * ang + dh;
    float d2 = ny * ang + dh;
    return fminf(d1*d1, d2*d2);
}

__global__ __launch_bounds__(256)
void ultrae_kernel(const float* __restrict__ emb,     // N_ENT x 512
                   const float* __restrict__ rboost,  // N_REL x 2
                   const float* __restrict__ rleft,   // N_REL x 512
                   const float* __restrict__ rright,  // N_REL x 512
                   const float* __restrict__ bias_h,  // N_ENT
                   const float* __restrict__ bias_t,  // N_ENT
                   const int*   __restrict__ u_idx,   // B
                   const int*   __restrict__ r_idx,   // B
                   const int*   __restrict__ v_idx,   // B x K
                   float*       __restrict__ out)     // B x K
{
    __shared__ __align__(16) float sx[DIM];
    __shared__ float red[8];
    __shared__ float sc[4];   // X0, X1, NX, bias_head[u]

    const int b    = blockIdx.x;
    const int tid  = threadIdx.x;
    const int lane = tid & 31;
    const int warp = tid >> 5;

    const int u = u_idx[b];
    const int r = r_idx[b];

    // ---------------- head transform (once per block) ----------------
    // each thread owns givens pair p = tid -> elements (2p, 2p+1)
    float2 h = ((const float2*)(emb + (size_t)u * DIM))[tid];
    if (tid == 0) h.x = 0.f;   // proj_tan0
    float part = (tid == 0) ? (-h.y * h.y) : (h.x*h.x + h.y*h.y);
    #pragma unroll
    for (int o = 16; o; o >>= 1) part += __shfl_xor_sync(0xffffffffu, part, o);
    if (lane == 0) red[warp] = part;
    __syncthreads();
    if (warp == 0) {
        float v = (lane < 8) ? red[lane] : 0.f;
        #pragma unroll
        for (int o = 4; o; o >>= 1) v += __shfl_xor_sync(0xffffffffu, v, o);
        if (lane == 0) red[0] = v;
    }
    __syncthreads();
    const float a = red[0];

    float c, s;
    if (a > 0.f) {
        float sp = sqrtf(fmaxf(a, EPSF));
        c = coshf(sp);
        s = sinhf(sp) / sp;
    } else {
        float st = sqrtf(fmaxf(-a, EPSF));
        c = cosf(st);
        s = sinf(st) / st;
    }
    float x0 = (tid == 0) ? c : s * h.x;
    float x1 = s * h.y;

    // givens rotation with r_right
    {
        float2 g = ((const float2*)(rright + (size_t)r * DIM))[tid];
        float gn = fmaxf(sqrtf(g.x*g.x + g.y*g.y), 1e-15f);
        float rc = g.x / gn, rs = g.y / gn;
        float y0 = rc*x0 - rs*x1;
        float y1 = rc*x1 + rs*x0;
        sx[2*tid]   = y0;
        sx[2*tid+1] = y1;
    }
    __syncthreads();

    // boost (only touches 0,1,510,511)
    if (tid == 0) {
        float z0 = rboost[2*r + 0], z1 = rboost[2*r + 1];
        float b0 = log1pf(expf(z0));        // softplus
        float b1 = log1pf(expf(z1));
        float C0 = sqrtf(1.f + b0*b0), C1 = sqrtf(1.f + b1*b1);
        float a0 = sx[0], a1 = sx[1], a510 = sx[510], a511 = sx[511];
        sx[0]   = C0*a0   - b0*a510;
        sx[1]   = C1*a1   - b1*a511;
        sx[510] = C0*a510 - b0*a0;
        sx[511] = C1*a511 - b1*a1;
    }
    __syncthreads();

    // givens reflection with r_left
    {
        float w0 = sx[2*tid], w1 = sx[2*tid+1];
        float2 g = ((const float2*)(rleft + (size_t)r * DIM))[tid];
        float gn = fmaxf(sqrtf(g.x*g.x + g.y*g.y), 1e-15f);
        float lc = g.x / gn, ls = g.y / gn;
        sx[2*tid]   = lc*w0 + ls*w1;
        sx[2*tid+1] = ls*w0 - lc*w1;
    }
    __syncthreads();

    if (tid == 0) {
        float X0 = sx[0], X1 = sx[1];
        sc[0] = X0;
        sc[1] = X1;
        sc[2] = sqrtf(X0*X0 + X1*X1);
        sc[3] = bias_h[u];
    }
    __syncthreads();

    const float X0 = sc[0], X1 = sc[1], NX = sc[2], BH = sc[3];

    // cache this lane's head slice in registers (same slots for every tail)
    const float4* sx4 = (const float4*)sx;
    const float4 xr0 = sx4[lane +  0];
    const float4 xr1 = sx4[lane + 32];
    const float4 xr2 = sx4[lane + 64];
    const float4 xr3 = sx4[lane + 96];

    // ---------------- tail loop: warp per tail, 2 tails in flight ----------------
    // this warp covers tails k = warp + 8*m, m = 0..15.
    // preload all 16 indices + their bias_t into lanes 0..15, broadcast by shuffle.
    const int* vrow = v_idx + b * NK;
    float* orow = out + b * NK;

    int   myv  = 0;
    float mybt = 0.f;
    if (lane < 16) {
        myv  = vrow[warp + 8 * lane];
        mybt = bias_t[myv];
    }

    // prime addresses for m = 0
    int vA = __shfl_sync(0xffffffffu, myv, 0);
    int vB = __shfl_sync(0xffffffffu, myv, 8);
    const float4* ta = (const float4*)(emb + (size_t)vA * DIM);
    const float4* tb = (const float4*)(emb + (size_t)vB * DIM);

    #pragma unroll 2
    for (int m = 0; m < 8; ++m) {
        const int kA = warp + 8 * m;
        const int kB = kA + 64;

        float4 A0 = ta[lane +  0], A1 = ta[lane + 32], A2 = ta[lane + 64], A3 = ta[lane + 96];
        float4 B0 = tb[lane +  0], B1 = tb[lane + 32], B2 = tb[lane + 64], B3 = tb[lane + 96];

        // next iteration's addresses (register-resident; overlaps with math below)
        if (m < 7) {
            int nvA = __shfl_sync(0xffffffffu, myv, m + 1);
            int nvB = __shfl_sync(0xffffffffu, myv, m + 9);
            ta = (const float4*)(emb + (size_t)nvA * DIM);
            tb = (const float4*)(emb + (size_t)nvB * DIM);
        }
        const float btA = __shfl_sync(0xffffffffu, mybt, m);
        const float btB = __shfl_sync(0xffffffffu, mybt, m + 8);

        float sqA = sq4(A0) + sq4(A1) + sq4(A2) + sq4(A3);
        float dpA = dot4(xr0, A0) + dot4(xr1, A1) + dot4(xr2, A2) + dot4(xr3, A3);
        float sqB = sq4(B0) + sq4(B1) + sq4(B2) + sq4(B3);
        float dpB = dot4(xr0, B0) + dot4(xr1, B1) + dot4(xr2, B2) + dot4(xr3, B3);

        float t1A = 0.f, t1B = 0.f;
        if (lane == 0) {
            // elements 0,1 are the time components: exclude from spatial sums
            t1A = A0.y;
            sqA -= A0.x*A0.x + A0.y*A0.y;
            dpA -= xr0.x*A0.x + xr0.y*A0.y;
            t1B = B0.y;
            sqB -= B0.x*B0.x + B0.y*B0.y;
            dpB -= xr0.x*B0.x + xr0.y*B0.y;
        }

        #pragma unroll
        for (int o = 16; o; o >>= 1) {
            sqA += __shfl_xor_sync(0xffffffffu, sqA, o);
            dpA += __shfl_xor_sync(0xffffffffu, dpA, o);
            sqB += __shfl_xor_sync(0xffffffffu, sqB, o);
            dpB += __shfl_xor_sync(0xffffffffu, dpB, o);
        }
        t1A = __shfl_sync(0xffffffffu, t1A, 0);
        t1B = __shfl_sync(0xffffffffu, t1B, 0);

        if (lane == 0) {
            float dA = tail_dist(sqA, dpA, t1A, X0, X1, NX);
            float dB = tail_dist(sqB, dpB, t1B, X0, X1, NX);
            orow[kA] = MARGINF - dA + BH + btA;
            orow[kB] = MARGINF - dB + BH + btB;
        }
    }
}

extern "C" void kernel_launch(void* const* d_in, const int* in_sizes, int n_in,
                              void* d_out, int out_size) {
    const float* emb    = (const float*)d_in[0];
    const float* rboost = (const float*)d_in[1];
    const float* rleft  = (const float*)d_in[2];
    const float* rright = (const float*)d_in[3];
    const float* bias_h = (const float*)d_in[4];
    const float* bias_t = (const float*)d_in[5];
    const int*   u_idx  = (const int*)d_in[6];
    const int*   r_idx  = (const int*)d_in[7];
    const int*   v_idx  = (const int*)d_in[8];
    ultrae_kernel<<<NB, 256>>>(emb, rboost, rleft, rright,
                               bias_h, bias_t, u_idx, r_idx, v_idx,
                               (float*)d_out);
}

// round 17
// speedup vs baseline: 1.4633x; 1.4633x over previous
#include <cuda_runtime.h>

#define DIM 512
#define TIME_DIM 2
#define NB 512
#define NK 128
#define EPSF 1e-6f
#define MARGINF 2.0f

__device__ __forceinline__ float dot4(float4 a, float4 b) {
    return a.x*b.x + a.y*b.y + a.z*b.z + a.w*b.w;
}
__device__ __forceinline__ float sq4(float4 a) {
    return a.x*a.x + a.y*a.y + a.z*a.z + a.w*a.w;
}

// per-tail scalar epilogue: mirrors reference manhattan_sqdist on both orders
__device__ __forceinline__ float tail_dist(float sq, float dp, float t1,
                                           float X0, float X1, float NX) {
    // a = -t1^2 + sum_{i>=2} t_i^2
    float a = sq - t1*t1;
    float ct, st;
    if (a > 0.f) {
        float sp = sqrtf(fmaxf(a, EPSF));
        ct = coshf(sp);
        st = sinhf(sp) / sp;
    } else {
        float q = sqrtf(fmaxf(-a, EPSF));
        ct = cosf(q);
        st = sinf(q) / q;
    }
    float y0 = ct;
    float y1 = st * t1;
    float ny = sqrtf(y0*y0 + y1*y1);
    float dt = X0*y0 + X1*y1;
    float ca = fminf(fmaxf(dt / (NX * ny), -1.f + EPSF), 1.f - EPSF);
    float ang = acosf(ca);
    float inner = NX * ny - st * dp;          // xs . ys = st * (x_s . t_raw_s)
    float dh = acoshf(fmaxf(inner, 1.f + EPSF));
    float d1 = NX * ang + dh;
    float d2 = ny * ang + dh;
    return fminf(d1*d1, d2*d2);
}

__global__ __launch_bounds__(256, 4)   // 4 CTAs/SM -> grid 512 fits in ONE wave (592 slots)
void ultrae_kernel(const float* __restrict__ emb,     // N_ENT x 512
                   const float* __restrict__ rboost,  // N_REL x 2
                   const float* __restrict__ rleft,   // N_REL x 512
                   const float* __restrict__ rright,  // N_REL x 512
                   const float* __restrict__ bias_h,  // N_ENT
                   const float* __restrict__ bias_t,  // N_ENT
                   const int*   __restrict__ u_idx,   // B
                   const int*   __restrict__ r_idx,   // B
                   const int*   __restrict__ v_idx,   // B x K
                   float*       __restrict__ out)     // B x K
{
    __shared__ __align__(16) float sx[DIM];
    __shared__ float red[8];
    __shared__ float sc[4];   // X0, X1, NX, bias_head[u]

    const int b    = blockIdx.x;
    const int tid  = threadIdx.x;
    const int lane = tid & 31;
    const int warp = tid >> 5;

    const int u = u_idx[b];
    const int r = r_idx[b];

    // ---------------- head transform (once per block) ----------------
    // each thread owns givens pair p = tid -> elements (2p, 2p+1)
    float2 h = ((const float2*)(emb + (size_t)u * DIM))[tid];
    if (tid == 0) h.x = 0.f;   // proj_tan0
    float part = (tid == 0) ? (-h.y * h.y) : (h.x*h.x + h.y*h.y);
    #pragma unroll
    for (int o = 16; o; o >>= 1) part += __shfl_xor_sync(0xffffffffu, part, o);
    if (lane == 0) red[warp] = part;
    __syncthreads();
    if (warp == 0) {
        float v = (lane < 8) ? red[lane] : 0.f;
        #pragma unroll
        for (int o = 4; o; o >>= 1) v += __shfl_xor_sync(0xffffffffu, v, o);
        if (lane == 0) red[0] = v;
    }
    __syncthreads();
    const float a = red[0];

    float c, s;
    if (a > 0.f) {
        float sp = sqrtf(fmaxf(a, EPSF));
        c = coshf(sp);
        s = sinhf(sp) / sp;
    } else {
        float st = sqrtf(fmaxf(-a, EPSF));
        c = cosf(st);
        s = sinf(st) / st;
    }
    float x0 = (tid == 0) ? c : s * h.x;
    float x1 = s * h.y;

    // givens rotation with r_right
    {
        float2 g = ((const float2*)(rright + (size_t)r * DIM))[tid];
        float gn = fmaxf(sqrtf(g.x*g.x + g.y*g.y), 1e-15f);
        float rc = g.x / gn, rs = g.y / gn;
        float y0 = rc*x0 - rs*x1;
        float y1 = rc*x1 + rs*x0;
        sx[2*tid]   = y0;
        sx[2*tid+1] = y1;
    }
    __syncthreads();

    // boost (only touches 0,1,510,511)
    if (tid == 0) {
        float z0 = rboost[2*r + 0], z1 = rboost[2*r + 1];
        float b0 = log1pf(expf(z0));        // softplus
        float b1 = log1pf(expf(z1));
        float C0 = sqrtf(1.f + b0*b0), C1 = sqrtf(1.f + b1*b1);
        float a0 = sx[0], a1 = sx[1], a510 = sx[510], a511 = sx[511];
        sx[0]   = C0*a0   - b0*a510;
        sx[1]   = C1*a1   - b1*a511;
        sx[510] = C0*a510 - b0*a0;
        sx[511] = C1*a511 - b1*a1;
    }
    __syncthreads();

    // givens reflection with r_left
    {
        float w0 = sx[2*tid], w1 = sx[2*tid+1];
        float2 g = ((const float2*)(rleft + (size_t)r * DIM))[tid];
        float gn = fmaxf(sqrtf(g.x*g.x + g.y*g.y), 1e-15f);
        float lc = g.x / gn, ls = g.y / gn;
        sx[2*tid]   = lc*w0 + ls*w1;
        sx[2*tid+1] = ls*w0 - lc*w1;
    }
    __syncthreads();

    if (tid == 0) {
        float X0 = sx[0], X1 = sx[1];
        sc[0] = X0;
        sc[1] = X1;
        sc[2] = sqrtf(X0*X0 + X1*X1);
        sc[3] = bias_h[u];
    }
    __syncthreads();

    const float X0 = sc[0], X1 = sc[1], NX = sc[2], BH = sc[3];
    const float4* sx4 = (const float4*)sx;   // head slice stays in smem; read in-loop
                                             // (ptxas hoists to regs only if pressure allows)

    // ---------------- tail loop: warp per tail, 2 tails in flight ----------------
    // this warp covers tails k = warp + 8*m, m = 0..15.
    // preload all 16 indices + their bias_t into lanes 0..15, broadcast by shuffle.
    const int* vrow = v_idx + b * NK;
    float* orow = out + b * NK;

    int   myv  = 0;
    float mybt = 0.f;
    if (lane < 16) {
        myv  = vrow[warp + 8 * lane];
        mybt = bias_t[myv];
    }

    // prime addresses for m = 0
    int vA = __shfl_sync(0xffffffffu, myv, 0);
    int vB = __shfl_sync(0xffffffffu, myv, 8);
    const float4* ta = (const float4*)(emb + (size_t)vA * DIM);
    const float4* tb = (const float4*)(emb + (size_t)vB * DIM);

    #pragma unroll 2
    for (int m = 0; m < 8; ++m) {
        const int kA = warp + 8 * m;
        const int kB = kA + 64;

        float4 A0 = ta[lane +  0], A1 = ta[lane + 32], A2 = ta[lane + 64], A3 = ta[lane + 96];
        float4 B0 = tb[lane +  0], B1 = tb[lane + 32], B2 = tb[lane + 64], B3 = tb[lane + 96];

        // next iteration's addresses (register-resident; overlaps with math below)
        if (m < 7) {
            int nvA = __shfl_sync(0xffffffffu, myv, m + 1);
            int nvB = __shfl_sync(0xffffffffu, myv, m + 9);
            ta = (const float4*)(emb + (size_t)nvA * DIM);
            tb = (const float4*)(emb + (size_t)nvB * DIM);
        }
        const float btA = __shfl_sync(0xffffffffu, mybt, m);
        const float btB = __shfl_sync(0xffffffffu, mybt, m + 8);

        float sqA = sq4(A0) + sq4(A1) + sq4(A2) + sq4(A3);
        float sqB = sq4(B0) + sq4(B1) + sq4(B2) + sq4(B3);

        // head slice read from smem inside the loop: each xq serves both A and B,
        // and under the 64-reg bound ptxas keeps these as LDS (no local spill).
        float dpA, dpB;
        {
            float4 xq = sx4[lane +  0];
            dpA = dot4(xq, A0);  dpB = dot4(xq, B0);
            xq = sx4[lane + 32];
            dpA += dot4(xq, A1); dpB += dot4(xq, B1);
            xq = sx4[lane + 64];
            dpA += dot4(xq, A2); dpB += dot4(xq, B2);
            xq = sx4[lane + 96];
            dpA += dot4(xq, A3); dpB += dot4(xq, B3);
        }

        float t1A = 0.f, t1B = 0.f;
        if (lane == 0) {
            // elements 0,1 are the time components: exclude from spatial sums
            float4 x0q = sx4[0];
            t1A = A0.y;
            sqA -= A0.x*A0.x + A0.y*A0.y;
            dpA -= x0q.x*A0.x + x0q.y*A0.y;
            t1B = B0.y;
            sqB -= B0.x*B0.x + B0.y*B0.y;
            dpB -= x0q.x*B0.x + x0q.y*B0.y;
        }

        #pragma unroll
        for (int o = 16; o; o >>= 1) {
            sqA += __shfl_xor_sync(0xffffffffu, sqA, o);
            dpA += __shfl_xor_sync(0xffffffffu, dpA, o);
            sqB += __shfl_xor_sync(0xffffffffu, sqB, o);
            dpB += __shfl_xor_sync(0xffffffffu, dpB, o);
        }
        // butterfly leaves full sums in every lane; only t1B must hop 0 -> 1
        t1B = __shfl_sync(0xffffffffu, t1B, 0);

        // split the transcendental epilogue: lane 0 does tail A, lane 1 does tail B
        if (lane < 2) {
            const float sq = (lane == 0) ? sqA : sqB;
            const float dp = (lane == 0) ? dpA : dpB;
            const float t1 = (lane == 0) ? t1A : t1B;
            const float bt = (lane == 0) ? btA : btB;
            const int   k  = (lane == 0) ? kA  : kB;
            float d = tail_dist(sq, dp, t1, X0, X1, NX);
            orow[k] = MARGINF - d + BH + bt;
        }
    }
}

extern "C" void kernel_launch(void* const* d_in, const int* in_sizes, int n_in,
                              void* d_out, int out_size) {
    const float* emb    = (const float*)d_in[0];
    const float* rboost = (const float*)d_in[1];
    const float* rleft  = (const float*)d_in[2];
    const float* rright = (const float*)d_in[3];
    const float* bias_h = (const float*)d_in[4];
    const float* bias_t = (const float*)d_in[5];
    const int*   u_idx  = (const int*)d_in[6];
    const int*   r_idx  = (const int*)d_in[7];
    const int*   v_idx  = (const int*)d_in[8];
    ultrae_kernel<<<NB, 256>>>(emb, rboost, rleft, rright,
                               bias_h, bias_t, u_idx, r_idx, v_idx,
                               (float*)d_out);
}